// round 7
// baseline (speedup 1.0000x reference)
#include <cuda_runtime.h>
#include <cstdint>

// Problem constants
#define BB   128        // batch
#define IN_  1024
#define OUT_ 1024
#define NS   16         // i-dimension splits
#define LI   (IN_/NS)   // 64 i-values per split
#define NB   4          // batches per block (lower MLP_p1 -> less CTA spread)
#define NBG  (BB/NB)    // 32 batch groups
#define OT   256        // outs per block
#define OTG  (OUT_/OT)  // 4 out groups
#define O4   (OUT_/4)   // 256 float4 lanes over full OUT
#define OT4  (OT/4)     // 64 float4 lanes per block

// Scratch (allocation-free rule: __device__ globals)
__device__ float g_partial[NS * BB * OUT_];   // per-split partials, 8 MB
__device__ int   g_count[NBG * OTG];          // tile completion counters
                                              // (zero-init; finisher resets)

// ---------------------------------------------------------------------------
// Fused streaming + reduction kernel. Grid = NS*NBG*OTG = 2048 blocks of 128
// threads at occ 8 (50% warps): ~13.8 blocks/SM over >=2 waves, so the HW
// work-steal absorbs per-CTA completion spread (B300: spread is driven by
// front-batched LDG count; NB=4 keeps MLP_p1 low). Thread (g=t>>6, l=t&63)
// owns 2 batches (lb=g+2k) x 1 float4 of outs -> acc[2] ~56 regs, no spill
// at the 64-reg occ-8 bound. x staged via 1KB smem. softplus(ro) fused; bias
// folded into s==0 partials; eps via __ldcs (evict-first). Last s-block per
// (bg,z) tile reduces all 16 partials in fixed s-order (deterministic).
// ---------------------------------------------------------------------------
__global__ __launch_bounds__(128, 8)
void main_kernel(const float* __restrict__ x,
                 const float* __restrict__ mu,
                 const float* __restrict__ ro,
                 const float* __restrict__ eps,
                 const float* __restrict__ mu_bias,
                 const float* __restrict__ ro_bias,
                 const float* __restrict__ eps_bias,
                 float* __restrict__ out) {
    __shared__ float xs[NB][LI];          // 1 KB
    __shared__ int   s_last;

    const int bx = blockIdx.x;            // 0..2047
    const int s  = bx & (NS - 1);         // 0..15
    const int bg = (bx >> 4) & (NBG - 1); // 0..31
    const int z  = bx >> 9;               // 0..3
    const int t  = threadIdx.x;
    const int l  = t & (OT4 - 1);         // o float4 lane (0..63)
    const int g  = t >> 6;                // 0..1 batch class
    const int i0 = s * LI;
    const int b0 = bg * NB;
    const int oc = z * OT4 + l;           // float4 column in [0, O4)

    // Cooperative float4 load of x tile [4 b][64 i]: 64 float4s (threads 0-63)
    if (t < NB * (LI / 4)) {
        const int row = t >> 4;           // 0..3
        const int col = (t & 15) * 4;     // 0..60
        float4 v = *reinterpret_cast<const float4*>(
            x + (size_t)(b0 + row) * IN_ + i0 + col);
        *reinterpret_cast<float4*>(&xs[row][col]) = v;
    }
    __syncthreads();

    const float4* mu4 = reinterpret_cast<const float4*>(mu)  + (size_t)i0 * O4 + oc;
    const float4* ro4 = reinterpret_cast<const float4*>(ro)  + (size_t)i0 * O4 + oc;
    const float4* ep4 = reinterpret_cast<const float4*>(eps)
                        + ((size_t)b0 * IN_ + i0) * O4 + oc;

    float4 acc[2];

    // ---- ii = 0 peeled: pure multiply (initializes acc) ----
    {
        float4 ev[2];
#pragma unroll
        for (int k = 0; k < 2; k++) {
            const int lb = g + 2 * k;
            ev[k] = __ldcs(&ep4[(size_t)lb * IN_ * O4]);
        }
        const float4 rr = ro4[0];
        const float4 mw = mu4[0];
        float4 sg;
        sg.x = log1pf(__expf(rr.x));
        sg.y = log1pf(__expf(rr.y));
        sg.z = log1pf(__expf(rr.z));
        sg.w = log1pf(__expf(rr.w));
#pragma unroll
        for (int k = 0; k < 2; k++) {
            const int lb = g + 2 * k;
            const float xr = xs[lb][0];
            acc[k].x = xr * fmaf(ev[k].x, sg.x, mw.x);
            acc[k].y = xr * fmaf(ev[k].y, sg.y, mw.y);
            acc[k].z = xr * fmaf(ev[k].z, sg.z, mw.z);
            acc[k].w = xr * fmaf(ev[k].w, sg.w, mw.w);
        }
    }

    // ---- ii = 1 .. LI-1 ----
#pragma unroll 1
    for (int ii = 1; ii < LI; ii++) {
        float4 ev[2];
#pragma unroll
        for (int k = 0; k < 2; k++) {
            const int lb = g + 2 * k;
            ev[k] = __ldcs(&ep4[((size_t)lb * IN_ + ii) * O4]);
        }
        const float4 rr = ro4[(size_t)ii * O4];
        const float4 mw = mu4[(size_t)ii * O4];
        float4 sg;
        sg.x = log1pf(__expf(rr.x));
        sg.y = log1pf(__expf(rr.y));
        sg.z = log1pf(__expf(rr.z));
        sg.w = log1pf(__expf(rr.w));
#pragma unroll
        for (int k = 0; k < 2; k++) {
            const int lb = g + 2 * k;
            const float xr = xs[lb][ii];
            acc[k].x = fmaf(xr, fmaf(ev[k].x, sg.x, mw.x), acc[k].x);
            acc[k].y = fmaf(xr, fmaf(ev[k].y, sg.y, mw.y), acc[k].y);
            acc[k].z = fmaf(xr, fmaf(ev[k].z, sg.z, mw.z), acc[k].z);
            acc[k].w = fmaf(xr, fmaf(ev[k].w, sg.w, mw.w), acc[k].w);
        }
    }

    // ---- s==0 blocks fold in the bias term ----
    if (s == 0) {
        const float4 rb = reinterpret_cast<const float4*>(ro_bias)[oc];
        const float4 mb = reinterpret_cast<const float4*>(mu_bias)[oc];
        float4 sb;
        sb.x = log1pf(__expf(rb.x));
        sb.y = log1pf(__expf(rb.y));
        sb.z = log1pf(__expf(rb.z));
        sb.w = log1pf(__expf(rb.w));
#pragma unroll
        for (int k = 0; k < 2; k++) {
            const int lb = g + 2 * k;
            const float4 eb = reinterpret_cast<const float4*>(eps_bias)
                                  [(size_t)(b0 + lb) * O4 + oc];
            acc[k].x = fmaf(eb.x, sb.x, acc[k].x + mb.x);
            acc[k].y = fmaf(eb.y, sb.y, acc[k].y + mb.y);
            acc[k].z = fmaf(eb.z, sb.z, acc[k].z + mb.z);
            acc[k].w = fmaf(eb.w, sb.w, acc[k].w + mb.w);
        }
    }

    // ---- write partials P[s][b][o] ----
    float4* Pbase = reinterpret_cast<float4*>(g_partial);
#pragma unroll
    for (int k = 0; k < 2; k++) {
        const int lb = g + 2 * k;
        Pbase[((size_t)s * BB + b0 + lb) * O4 + oc] = acc[k];
    }

    // ---- last-block-done: 16th arriver for this (bg,z) tile reduces ----
    __threadfence();                       // release: partials visible
    __syncthreads();
    if (t == 0) {
        int prev = atomicAdd(&g_count[bg * OTG + z], 1);
        s_last = (prev == NS - 1);
    }
    __syncthreads();
    if (s_last) {
        __threadfence();                   // acquire: see all 16 partials
        if (t == 0) g_count[bg * OTG + z] = 0;   // reset for next replay
#pragma unroll
        for (int k = 0; k < 2; k++) {
            const int lb = g + 2 * k;
            const float4* Pc = Pbase + ((size_t)b0 + lb) * O4 + oc;
            // Fixed s-ascending order -> deterministic FP sum
            float4 r = Pc[0];
#pragma unroll
            for (int ss = 1; ss < NS; ss++) {
                float4 p = Pc[(size_t)ss * BB * O4];
                r.x += p.x; r.y += p.y; r.z += p.z; r.w += p.w;
            }
            reinterpret_cast<float4*>(out)[(size_t)(b0 + lb) * O4 + oc] = r;
        }
    }
}

// ---------------------------------------------------------------------------
// Launch. Input order (metadata): x, mu, ro, mu_bias, ro_bias, eps, eps_bias
// ---------------------------------------------------------------------------
extern "C" void kernel_launch(void* const* d_in, const int* in_sizes, int n_in,
                              void* d_out, int out_size) {
    const float* x        = (const float*)d_in[0];
    const float* mu       = (const float*)d_in[1];
    const float* ro       = (const float*)d_in[2];
    const float* mu_bias  = (const float*)d_in[3];
    const float* ro_bias  = (const float*)d_in[4];
    const float* eps      = (const float*)d_in[5];
    const float* eps_bias = (const float*)d_in[6];
    float* out = (float*)d_out;

    // Single fused kernel: 2048 blocks x 128 threads, occ 8
    main_kernel<<<NS * NBG * OTG, 128>>>(x, mu, ro, eps,
                                         mu_bias, ro_bias, eps_bias, out);
}

// round 8
// speedup vs baseline: 1.1591x; 1.1591x over previous
#include <cuda_runtime.h>
#include <cstdint>

// Problem constants
#define BB   128        // batch
#define IN_  1024
#define OUT_ 1024
#define NS   32         // i-dimension splits (halved block length -> 2+ waves)
#define LI   (IN_/NS)   // 32 i-values per split
#define NB   8          // batches per block (R6's proven amortization point)
#define NBG  (BB/NB)    // 16 batch groups
#define OT   256        // outs per block
#define OTG  (OUT_/OT)  // 4 out groups
#define O4   (OUT_/4)   // 256 float4 lanes over full OUT
#define OT4  (OT/4)     // 64 float4 lanes per block

// Scratch (allocation-free rule: __device__ globals)
__device__ float g_partial[NS * BB * OUT_];   // per-split partials, 16 MB
__device__ int   g_count[NBG * OTG];          // tile completion counters
                                              // (zero-init; finisher resets)

// ---------------------------------------------------------------------------
// Fused streaming + reduction kernel. Inner loop is IDENTICAL to the best
// (R6) config: NB=8, OT=256, acc[4], 128 threads, occ 7 (issue 49.5%,
// DRAM-fed). Only the i-axis is split finer (NS=32): grid = 2048 blocks of
// half length -> ~13.8 blocks/SM across >=2 waves, so work-stealing absorbs
// per-CTA completion spread and the end-of-kernel tail (the 21% DRAM-idle in
// R6's single-wave profile) halves. softplus(ro) fused; bias folded into
// s==0 partials; eps via __ldcs. Last s-block per (bg,z) tile sums all 32
// partials in fixed s-order (deterministic) and writes out.
// ---------------------------------------------------------------------------
__global__ __launch_bounds__(128, 7)
void main_kernel(const float* __restrict__ x,
                 const float* __restrict__ mu,
                 const float* __restrict__ ro,
                 const float* __restrict__ eps,
                 const float* __restrict__ mu_bias,
                 const float* __restrict__ ro_bias,
                 const float* __restrict__ eps_bias,
                 float* __restrict__ out) {
    __shared__ float xs[NB][LI];          // 1 KB
    __shared__ int   s_last;

    const int bx = blockIdx.x;            // 0..2047
    const int s  = bx & (NS - 1);         // 0..31
    const int bg = (bx >> 5) & (NBG - 1); // 0..15
    const int z  = bx >> 9;               // 0..3
    const int t  = threadIdx.x;
    const int l  = t & (OT4 - 1);         // o float4 lane (0..63)
    const int g  = t >> 6;                // 0..1 batch class
    const int i0 = s * LI;
    const int b0 = bg * NB;
    const int oc = z * OT4 + l;           // float4 column in [0, O4)

    // Cooperative float4 load of x tile [8 b][32 i]: 64 float4s (threads 0-63)
    if (t < NB * (LI / 4)) {
        const int row = t >> 3;           // 0..7
        const int col = (t & 7) * 4;      // 0..28
        float4 v = *reinterpret_cast<const float4*>(
            x + (size_t)(b0 + row) * IN_ + i0 + col);
        *reinterpret_cast<float4*>(&xs[row][col]) = v;
    }
    __syncthreads();

    const float4* mu4 = reinterpret_cast<const float4*>(mu)  + (size_t)i0 * O4 + oc;
    const float4* ro4 = reinterpret_cast<const float4*>(ro)  + (size_t)i0 * O4 + oc;
    const float4* ep4 = reinterpret_cast<const float4*>(eps)
                        + ((size_t)b0 * IN_ + i0) * O4 + oc;

    float4 acc[4];

    // ---- ii = 0 peeled: pure multiply (initializes acc) ----
    {
        float4 ev[4];
#pragma unroll
        for (int k = 0; k < 4; k++) {
            const int lb = g + 2 * k;
            ev[k] = __ldcs(&ep4[(size_t)lb * IN_ * O4]);
        }
        const float4 rr = ro4[0];
        const float4 mw = mu4[0];
        float4 sg;
        sg.x = log1pf(__expf(rr.x));
        sg.y = log1pf(__expf(rr.y));
        sg.z = log1pf(__expf(rr.z));
        sg.w = log1pf(__expf(rr.w));
#pragma unroll
        for (int k = 0; k < 4; k++) {
            const int lb = g + 2 * k;
            const float xr = xs[lb][0];
            acc[k].x = xr * fmaf(ev[k].x, sg.x, mw.x);
            acc[k].y = xr * fmaf(ev[k].y, sg.y, mw.y);
            acc[k].z = xr * fmaf(ev[k].z, sg.z, mw.z);
            acc[k].w = xr * fmaf(ev[k].w, sg.w, mw.w);
        }
    }

    // ---- ii = 1 .. LI-1 ----
#pragma unroll 1
    for (int ii = 1; ii < LI; ii++) {
        float4 ev[4];
#pragma unroll
        for (int k = 0; k < 4; k++) {
            const int lb = g + 2 * k;
            ev[k] = __ldcs(&ep4[((size_t)lb * IN_ + ii) * O4]);
        }
        const float4 rr = ro4[(size_t)ii * O4];
        const float4 mw = mu4[(size_t)ii * O4];
        float4 sg;
        sg.x = log1pf(__expf(rr.x));
        sg.y = log1pf(__expf(rr.y));
        sg.z = log1pf(__expf(rr.z));
        sg.w = log1pf(__expf(rr.w));
#pragma unroll
        for (int k = 0; k < 4; k++) {
            const int lb = g + 2 * k;
            const float xr = xs[lb][ii];
            acc[k].x = fmaf(xr, fmaf(ev[k].x, sg.x, mw.x), acc[k].x);
            acc[k].y = fmaf(xr, fmaf(ev[k].y, sg.y, mw.y), acc[k].y);
            acc[k].z = fmaf(xr, fmaf(ev[k].z, sg.z, mw.z), acc[k].z);
            acc[k].w = fmaf(xr, fmaf(ev[k].w, sg.w, mw.w), acc[k].w);
        }
    }

    // ---- s==0 blocks fold in the bias term ----
    if (s == 0) {
        const float4 rb = reinterpret_cast<const float4*>(ro_bias)[oc];
        const float4 mb = reinterpret_cast<const float4*>(mu_bias)[oc];
        float4 sb;
        sb.x = log1pf(__expf(rb.x));
        sb.y = log1pf(__expf(rb.y));
        sb.z = log1pf(__expf(rb.z));
        sb.w = log1pf(__expf(rb.w));
#pragma unroll
        for (int k = 0; k < 4; k++) {
            const int lb = g + 2 * k;
            const float4 eb = reinterpret_cast<const float4*>(eps_bias)
                                  [(size_t)(b0 + lb) * O4 + oc];
            acc[k].x = fmaf(eb.x, sb.x, acc[k].x + mb.x);
            acc[k].y = fmaf(eb.y, sb.y, acc[k].y + mb.y);
            acc[k].z = fmaf(eb.z, sb.z, acc[k].z + mb.z);
            acc[k].w = fmaf(eb.w, sb.w, acc[k].w + mb.w);
        }
    }

    // ---- write partials P[s][b][o] ----
    float4* Pbase = reinterpret_cast<float4*>(g_partial);
#pragma unroll
    for (int k = 0; k < 4; k++) {
        const int lb = g + 2 * k;
        Pbase[((size_t)s * BB + b0 + lb) * O4 + oc] = acc[k];
    }

    // ---- last-block-done: 32nd arriver for this (bg,z) tile reduces ----
    __threadfence();                       // release: partials visible
    __syncthreads();
    if (t == 0) {
        int prev = atomicAdd(&g_count[bg * OTG + z], 1);
        s_last = (prev == NS - 1);
    }
    __syncthreads();
    if (s_last) {
        __threadfence();                   // acquire: see all partials
        if (t == 0) g_count[bg * OTG + z] = 0;   // reset for next replay
#pragma unroll
        for (int k = 0; k < 4; k++) {
            const int lb = g + 2 * k;
            const float4* Pc = Pbase + ((size_t)b0 + lb) * O4 + oc;
            // Fixed s-ascending order -> deterministic FP sum
            float4 r = Pc[0];
#pragma unroll
            for (int ss = 1; ss < NS; ss++) {
                float4 p = Pc[(size_t)ss * BB * O4];
                r.x += p.x; r.y += p.y; r.z += p.z; r.w += p.w;
            }
            reinterpret_cast<float4*>(out)[(size_t)(b0 + lb) * O4 + oc] = r;
        }
    }
}

// ---------------------------------------------------------------------------
// Launch. Input order (metadata): x, mu, ro, mu_bias, ro_bias, eps, eps_bias
// ---------------------------------------------------------------------------
extern "C" void kernel_launch(void* const* d_in, const int* in_sizes, int n_in,
                              void* d_out, int out_size) {
    const float* x        = (const float*)d_in[0];
    const float* mu       = (const float*)d_in[1];
    const float* ro       = (const float*)d_in[2];
    const float* mu_bias  = (const float*)d_in[3];
    const float* ro_bias  = (const float*)d_in[4];
    const float* eps      = (const float*)d_in[5];
    const float* eps_bias = (const float*)d_in[6];
    float* out = (float*)d_out;

    // Single fused kernel: 2048 blocks x 128 threads, occ 7
    main_kernel<<<NS * NBG * OTG, 128>>>(x, mu, ro, eps,
                                         mu_bias, ro_bias, eps_bias, out);
}

// round 9
// speedup vs baseline: 1.2393x; 1.0692x over previous
#include <cuda_runtime.h>
#include <cstdint>

// Problem constants
#define BB   128        // batch
#define IN_  1024
#define OUT_ 1024
#define NS   16         // i-dimension splits (empirical optimum)
#define LI   (IN_/NS)   // 64 i-values per split
#define NB   8          // batches per block (amortization sweet spot)
#define NBG  (BB/NB)    // 16 batch groups
#define OT   256        // outs per block
#define OTG  (OUT_/OT)  // 4 out groups
#define O4   (OUT_/4)   // 256 float4 lanes over full OUT
#define OT4  (OT/4)     // 64 float4 lanes per block

// Scratch (allocation-free rule: __device__ global)
__device__ float g_partial[NS * BB * OUT_];   // per-split partials, 8 MB

// ---------------------------------------------------------------------------
// Main streaming kernel — R5's proven-fastest loop (82.3us): 1024 blocks of
// 128 threads, occ 7. Block (s,bg,z): i in [s*LI,(s+1)*LI), batches
// [bg*8,bg*8+8), outs [z*256,z*256+256). acc[4] float4/thread. x staged via
// 2KB smem. softplus(ro) fused; bias folded into s==0 partials. eps via
// __ldcs (evict-first: measured neutral for this loop, and it keeps the 8MB
// partials L2-resident for the reduce kernel).
// ---------------------------------------------------------------------------
__global__ __launch_bounds__(128, 7)
void main_kernel(const float* __restrict__ x,
                 const float* __restrict__ mu,
                 const float* __restrict__ ro,
                 const float* __restrict__ eps,
                 const float* __restrict__ mu_bias,
                 const float* __restrict__ ro_bias,
                 const float* __restrict__ eps_bias) {
    __shared__ float xs[NB][LI];          // 2 KB

    const int bx = blockIdx.x;            // 0..1023
    const int s  = bx & (NS - 1);         // 0..15
    const int bg = (bx >> 4) & (NBG - 1); // 0..15
    const int z  = bx >> 8;               // 0..3
    const int t  = threadIdx.x;
    const int l  = t & (OT4 - 1);         // o float4 lane (0..63)
    const int g  = t >> 6;                // 0..1 batch class
    const int i0 = s * LI;
    const int b0 = bg * NB;
    const int oc = z * OT4 + l;           // float4 column in [0, O4)

    // Cooperative float4 load of x tile [8 b][64 i]: 128 float4s, one each
    {
        const int row = t >> 4;           // 0..7
        const int col = (t & 15) * 4;     // 0..60
        float4 v = *reinterpret_cast<const float4*>(
            x + (size_t)(b0 + row) * IN_ + i0 + col);
        *reinterpret_cast<float4*>(&xs[row][col]) = v;
    }
    __syncthreads();

    const float4* mu4 = reinterpret_cast<const float4*>(mu)  + (size_t)i0 * O4 + oc;
    const float4* ro4 = reinterpret_cast<const float4*>(ro)  + (size_t)i0 * O4 + oc;
    const float4* ep4 = reinterpret_cast<const float4*>(eps)
                        + ((size_t)b0 * IN_ + i0) * O4 + oc;

    float4 acc[4];

    // ---- ii = 0 peeled: pure multiply (initializes acc) ----
    {
        float4 ev[4];
#pragma unroll
        for (int k = 0; k < 4; k++) {
            const int lb = g + 2 * k;
            ev[k] = __ldcs(&ep4[(size_t)lb * IN_ * O4]);
        }
        const float4 rr = ro4[0];
        const float4 mw = mu4[0];
        float4 sg;
        sg.x = log1pf(__expf(rr.x));
        sg.y = log1pf(__expf(rr.y));
        sg.z = log1pf(__expf(rr.z));
        sg.w = log1pf(__expf(rr.w));
#pragma unroll
        for (int k = 0; k < 4; k++) {
            const int lb = g + 2 * k;
            const float xr = xs[lb][0];
            acc[k].x = xr * fmaf(ev[k].x, sg.x, mw.x);
            acc[k].y = xr * fmaf(ev[k].y, sg.y, mw.y);
            acc[k].z = xr * fmaf(ev[k].z, sg.z, mw.z);
            acc[k].w = xr * fmaf(ev[k].w, sg.w, mw.w);
        }
    }

    // ---- ii = 1 .. LI-1 ----
#pragma unroll 1
    for (int ii = 1; ii < LI; ii++) {
        float4 ev[4];
#pragma unroll
        for (int k = 0; k < 4; k++) {
            const int lb = g + 2 * k;
            ev[k] = __ldcs(&ep4[((size_t)lb * IN_ + ii) * O4]);
        }
        const float4 rr = ro4[(size_t)ii * O4];
        const float4 mw = mu4[(size_t)ii * O4];
        float4 sg;
        sg.x = log1pf(__expf(rr.x));
        sg.y = log1pf(__expf(rr.y));
        sg.z = log1pf(__expf(rr.z));
        sg.w = log1pf(__expf(rr.w));
#pragma unroll
        for (int k = 0; k < 4; k++) {
            const int lb = g + 2 * k;
            const float xr = xs[lb][ii];
            acc[k].x = fmaf(xr, fmaf(ev[k].x, sg.x, mw.x), acc[k].x);
            acc[k].y = fmaf(xr, fmaf(ev[k].y, sg.y, mw.y), acc[k].y);
            acc[k].z = fmaf(xr, fmaf(ev[k].z, sg.z, mw.z), acc[k].z);
            acc[k].w = fmaf(xr, fmaf(ev[k].w, sg.w, mw.w), acc[k].w);
        }
    }

    // ---- s==0 blocks fold in the bias term ----
    if (s == 0) {
        const float4 rb = reinterpret_cast<const float4*>(ro_bias)[oc];
        const float4 mb = reinterpret_cast<const float4*>(mu_bias)[oc];
        float4 sb;
        sb.x = log1pf(__expf(rb.x));
        sb.y = log1pf(__expf(rb.y));
        sb.z = log1pf(__expf(rb.z));
        sb.w = log1pf(__expf(rb.w));
#pragma unroll
        for (int k = 0; k < 4; k++) {
            const int lb = g + 2 * k;
            const float4 eb = reinterpret_cast<const float4*>(eps_bias)
                                  [(size_t)(b0 + lb) * O4 + oc];
            acc[k].x = fmaf(eb.x, sb.x, acc[k].x + mb.x);
            acc[k].y = fmaf(eb.y, sb.y, acc[k].y + mb.y);
            acc[k].z = fmaf(eb.z, sb.z, acc[k].z + mb.z);
            acc[k].w = fmaf(eb.w, sb.w, acc[k].w + mb.w);
        }
    }

    // ---- write partials P[s][b][o] ----
    float4* Pbase = reinterpret_cast<float4*>(g_partial);
#pragma unroll
    for (int k = 0; k < 4; k++) {
        const int lb = g + 2 * k;
        Pbase[((size_t)s * BB + b0 + lb) * O4 + oc] = acc[k];
    }
}

// ---------------------------------------------------------------------------
// Reduce: 4-way-split s-sum for 4x parallelism (128K threads vs 32K).
// Thread (q=t>>5, lane=t&31) sums partials s in [4q, 4q+4) for output lane
// L = blockIdx*32+lane, then quarters combine via smem in fixed q-order
// (deterministic). 4 independent LDG.128/thread; partials are L2-hot.
// ---------------------------------------------------------------------------
__global__ __launch_bounds__(128)
void reduce_kernel(float* __restrict__ out) {
    __shared__ float4 red[4][32];

    const int t    = threadIdx.x;
    const int lane = t & 31;
    const int q    = t >> 5;                       // 0..3
    const int L    = blockIdx.x * 32 + lane;       // 0..BB*O4-1

    const float4* Pc = reinterpret_cast<const float4*>(g_partial) + L;

    // Fixed ascending order within quarter
    float4 r = Pc[(size_t)(q * 4) * BB * O4];
#pragma unroll
    for (int j = 1; j < 4; j++) {
        float4 p = Pc[(size_t)(q * 4 + j) * BB * O4];
        r.x += p.x; r.y += p.y; r.z += p.z; r.w += p.w;
    }
    red[q][lane] = r;
    __syncthreads();

    if (q == 0) {
        // Fixed quarter order -> deterministic
        float4 a = red[0][lane];
#pragma unroll
        for (int j = 1; j < 4; j++) {
            float4 p = red[j][lane];
            a.x += p.x; a.y += p.y; a.z += p.z; a.w += p.w;
        }
        reinterpret_cast<float4*>(out)[L] = a;
    }
}

// ---------------------------------------------------------------------------
// Launch. Input order (metadata): x, mu, ro, mu_bias, ro_bias, eps, eps_bias
// ---------------------------------------------------------------------------
extern "C" void kernel_launch(void* const* d_in, const int* in_sizes, int n_in,
                              void* d_out, int out_size) {
    const float* x        = (const float*)d_in[0];
    const float* mu       = (const float*)d_in[1];
    const float* ro       = (const float*)d_in[2];
    const float* mu_bias  = (const float*)d_in[3];
    const float* ro_bias  = (const float*)d_in[4];
    const float* eps      = (const float*)d_in[5];
    const float* eps_bias = (const float*)d_in[6];
    float* out = (float*)d_out;

    // Main: 1024 blocks x 128 threads, occ 7 (proven fastest streaming loop)
    main_kernel<<<NS * NBG * OTG, 128>>>(x, mu, ro, eps,
                                         mu_bias, ro_bias, eps_bias);

    // Reduce: 1024 blocks x 128 threads (4-way split s-sum)
    reduce_kernel<<<(BB * O4) / 32, 128>>>(out);
}